// round 1
// baseline (speedup 1.0000x reference)
#include <cuda_runtime.h>
#include <stdint.h>

#define NN 100000
#define EE 1600000
#define NSLICE 32
#define SLOPE 0.01f
#define BN_EPS 1e-5f

typedef unsigned long long ull;

// ------------------------- device scratch (no allocs allowed) ----------------
__device__ float g_t1[NN * 64];        // prop(x)
__device__ float g_h1[NN * 128];       // layer1 pre-BN
__device__ float g_d2[NN * 64];        // h1p @ W2[0]
__device__ float g_z2[NN * 64];        // dinv * (h1p @ W2[1])
__device__ float g_h2[NN * 64];        // layer2 pre-BN
__device__ float g_d3[NN * 64];
__device__ float g_z3[NN * 64];
__device__ int   g_deg[NN];
__device__ int   g_cnt[NN];
__device__ int   g_ptr[NN + 1];
__device__ int   g_fill[NN];
__device__ int   g_src[EE];
__device__ float g_dinv[NN];
__device__ int   g_bsum[256];
__device__ float g_sum1[NSLICE * 128], g_sq1[NSLICE * 128];
__device__ float g_sum2[NSLICE * 64],  g_sq2[NSLICE * 64];
__device__ float g_a1[128], g_c1[128], g_a2[64], g_c2[64];

// ------------------------- small helpers -------------------------------------
__device__ __forceinline__ ull ffma2(ull a, ull b, ull c) {
    ull d;
    asm("fma.rn.f32x2 %0, %1, %2, %3;" : "=l"(d) : "l"(a), "l"(b), "l"(c));
    return d;
}
__device__ __forceinline__ ull pack2dup(float v) {
    ull r;
    asm("mov.b64 %0, {%1, %1};" : "=l"(r) : "f"(v));
    return r;
}
__device__ __forceinline__ void unpack2(ull v, float& lo, float& hi) {
    asm("mov.b64 {%0, %1}, %2;" : "=f"(lo), "=f"(hi) : "l"(v));
}

// ------------------------- setup kernels -------------------------------------
__global__ void zero_k() {
    int i = blockIdx.x * blockDim.x + threadIdx.x;
    if (i < NN) { g_deg[i] = 0; g_cnt[i] = 0; }
    if (i < NSLICE * 128) { g_sum1[i] = 0.f; g_sq1[i] = 0.f; }
    if (i < NSLICE * 64)  { g_sum2[i] = 0.f; g_sq2[i] = 0.f; }
}

__global__ void hist_k(const int* __restrict__ ei) {
    int e = blockIdx.x * blockDim.x + threadIdx.x;
    if (e < EE) {
        atomicAdd(&g_deg[ei[e]], 1);
        atomicAdd(&g_cnt[ei[EE + e]], 1);
    }
}

__global__ void dinv_k() {
    int i = blockIdx.x * blockDim.x + threadIdx.x;
    if (i < NN) {
        int d = g_deg[i];
        g_dinv[i] = (d > 0) ? rsqrtf((float)d) : 0.f;
    }
}

__device__ __forceinline__ int block_scan_incl(int v, int* sm) {
    int lane = threadIdx.x & 31, w = threadIdx.x >> 5;
    int incl = v;
#pragma unroll
    for (int o = 1; o < 32; o <<= 1) {
        int n = __shfl_up_sync(0xffffffffu, incl, o);
        if (lane >= o) incl += n;
    }
    if (lane == 31) sm[w] = incl;
    __syncthreads();
    if (w == 0) {
        int nw = blockDim.x >> 5;
        int s = (lane < nw) ? sm[lane] : 0;
#pragma unroll
        for (int o = 1; o < 32; o <<= 1) {
            int n = __shfl_up_sync(0xffffffffu, s, o);
            if (lane >= o) s += n;
        }
        sm[lane] = s;
    }
    __syncthreads();
    if (w > 0) incl += sm[w - 1];
    return incl;
}

__global__ void scanA_k() {
    __shared__ int sm[32];
    int i = blockIdx.x * 1024 + threadIdx.x;
    int v = (i < NN) ? g_cnt[i] : 0;
    int incl = block_scan_incl(v, sm);
    if (i < NN) g_ptr[i] = incl - v;             // local exclusive
    if (threadIdx.x == 1023) g_bsum[blockIdx.x] = incl;
}

__global__ void scanB_k() {
    __shared__ int sm[32];
    int t = threadIdx.x;
    int v = (t < 98) ? g_bsum[t] : 0;
    int incl = block_scan_incl(v, sm);
    if (t < 98) g_bsum[t] = incl - v;            // exclusive block offsets
}

__global__ void scanC_k() {
    int i = blockIdx.x * 1024 + threadIdx.x;
    if (i < NN) {
        int p = g_ptr[i] + g_bsum[blockIdx.x];
        g_ptr[i] = p;
        g_fill[i] = p;
    }
    if (i == 0) g_ptr[NN] = EE;
}

__global__ void fill_k(const int* __restrict__ ei) {
    int e = blockIdx.x * blockDim.x + threadIdx.x;
    if (e < EE) {
        int c = ei[EE + e];
        int pos = atomicAdd(&g_fill[c], 1);
        g_src[pos] = ei[e];
    }
}

// ------------------------- SpMM: one warp per destination node ---------------
// out[d] = (EPI2 ? direct[d] + bias : 0) - dinv[d] * sum_{s in in(d)} w(s)*feat[s]
// w(s) = dinv[s] if SCALE_SRC else 1 (feat pre-scaled).
template <bool SCALE_SRC, bool EPI2, bool STATS>
__global__ __launch_bounds__(256) void spmm_k(
    const float2* __restrict__ feat, const float* __restrict__ dinv,
    const int* __restrict__ ptr, const int* __restrict__ srci,
    const float2* __restrict__ direct, const float2* __restrict__ bias2,
    float2* __restrict__ out, float* __restrict__ ssum, float* __restrict__ ssq)
{
    int lane = threadIdx.x & 31, warp = threadIdx.x >> 5;
    int d = blockIdx.x * 8 + warp;
    float2 res = make_float2(0.f, 0.f);
    bool valid = (d < NN);
    if (valid) {
        int e0 = __ldg(&ptr[d]);
        int e1 = __ldg(&ptr[d + 1]);
        float ax = 0.f, ay = 0.f;
        int e = e0;
        for (; e + 4 <= e1; e += 4) {
            int s0 = __ldg(&srci[e]);
            int s1 = __ldg(&srci[e + 1]);
            int s2 = __ldg(&srci[e + 2]);
            int s3 = __ldg(&srci[e + 3]);
            float2 f0 = __ldg(&feat[(size_t)s0 * 32 + lane]);
            float2 f1 = __ldg(&feat[(size_t)s1 * 32 + lane]);
            float2 f2 = __ldg(&feat[(size_t)s2 * 32 + lane]);
            float2 f3 = __ldg(&feat[(size_t)s3 * 32 + lane]);
            float w0 = SCALE_SRC ? __ldg(&dinv[s0]) : 1.f;
            float w1 = SCALE_SRC ? __ldg(&dinv[s1]) : 1.f;
            float w2 = SCALE_SRC ? __ldg(&dinv[s2]) : 1.f;
            float w3 = SCALE_SRC ? __ldg(&dinv[s3]) : 1.f;
            ax += w0 * f0.x + w1 * f1.x + w2 * f2.x + w3 * f3.x;
            ay += w0 * f0.y + w1 * f1.y + w2 * f2.y + w3 * f3.y;
        }
        for (; e < e1; e++) {
            int s = __ldg(&srci[e]);
            float2 f = __ldg(&feat[(size_t)s * 32 + lane]);
            float w = SCALE_SRC ? __ldg(&dinv[s]) : 1.f;
            ax += w * f.x;
            ay += w * f.y;
        }
        float di = __ldg(&dinv[d]);
        if (EPI2) {
            float2 dv = __ldg(&direct[(size_t)d * 32 + lane]);
            float2 b = __ldg(&bias2[lane]);
            res.x = dv.x + b.x - di * ax;
            res.y = dv.y + b.y - di * ay;
        } else {
            res.x = -di * ax;
            res.y = -di * ay;
        }
        out[(size_t)d * 32 + lane] = res;
    }
    if (STATS) {
        __shared__ float ss[64], sq[64];
        int t = threadIdx.x;
        if (t < 64) { ss[t] = 0.f; sq[t] = 0.f; }
        __syncthreads();
        if (valid) {
            atomicAdd(&ss[2 * lane], res.x);
            atomicAdd(&ss[2 * lane + 1], res.y);
            atomicAdd(&sq[2 * lane], res.x * res.x);
            atomicAdd(&sq[2 * lane + 1], res.y * res.y);
        }
        __syncthreads();
        if (t < 64) {
            int sl = blockIdx.x & (NSLICE - 1);
            atomicAdd(&ssum[sl * 64 + t], ss[t]);
            atomicAdd(&ssq[sl * 64 + t], sq[t]);
        }
    }
}

// ------------------------- SGEMM (128x128 tile, f32x2 inner loop) -----------
// C[m][n] = sum_k Atrans(A[m][k]) * B[k][n]   (Cout fixed = 128)
// TWO_A   : k<64 -> A1 (ld 64), k>=64 -> A2 (ld 64); else A1 with ld KTOT.
// BN_IN   : A element transform lrelu(bna[k]*v + bnc[k])
// SPLIT_B : B cols 0-63 from Wa (ld 64), 64-127 from Wb (ld 64); else Wa ld 128.
// SPLIT_OUT: cols 0-63 -> outA (ld 64); cols 64-127 -> outB (ld 64) scaled by dinv[row]
// BIAS    : add bias[col] (only used with !SPLIT_OUT)
// STATS   : accumulate per-column sum / sum-sq of C into sliced globals
template <int KTOT, bool TWO_A, bool BN_IN, bool SPLIT_B, bool SPLIT_OUT, bool BIAS, bool STATS>
__global__ __launch_bounds__(256, 2) void gemm_k(
    const float* __restrict__ A1, const float* __restrict__ A2,
    const float* __restrict__ Wa, const float* __restrict__ Wb,
    const float* __restrict__ bias,
    const float* __restrict__ bna, const float* __restrict__ bnc,
    const float* __restrict__ dinv,
    float* __restrict__ outA, float* __restrict__ outB,
    float* __restrict__ ssum, float* __restrict__ ssq)
{
    __shared__ float As[8][128];
    __shared__ float Bs[8][128];
    __shared__ float bnA[128], bnC[128];
    __shared__ float scol[128], scq[128];

    const int tid = threadIdx.x;
    const int tx = tid & 15, ty = tid >> 4;
    const int m0 = blockIdx.x * 128;

    if (BN_IN && tid < KTOT) { bnA[tid] = bna[tid]; bnC[tid] = bnc[tid]; }

    // loader indices
    const int am = tid >> 1;          // 0..127  (row within tile)
    const int ak = (tid & 1) * 4;     // 0 or 4  (k offset within BK)
    const int bk = tid >> 5;          // 0..7
    const int bn = (tid & 31) * 4;    // 0..124

    ull acc2[4][8];
#pragma unroll
    for (int i = 0; i < 4; i++)
#pragma unroll
        for (int j = 0; j < 8; j++) acc2[i][j] = 0ull;

    __syncthreads();   // bnA/bnC visible

    for (int k0 = 0; k0 < KTOT; k0 += 8) {
        // ---- A tile load (global -> regs) ----
        float4 av = make_float4(0.f, 0.f, 0.f, 0.f);
        int r = m0 + am;
        if (r < NN) {
            int kg = k0 + ak;
            const float* src;
            if (TWO_A)
                src = (kg < 64) ? (A1 + (size_t)r * 64 + kg)
                                : (A2 + (size_t)r * 64 + (kg - 64));
            else
                src = A1 + (size_t)r * KTOT + kg;
            av = *(const float4*)src;
        }
        if (BN_IN) {
            float* pv = &av.x;
#pragma unroll
            for (int i = 0; i < 4; i++) {
                float v = pv[i] * bnA[k0 + ak + i] + bnC[k0 + ak + i];
                pv[i] = (v >= 0.f) ? v : SLOPE * v;
            }
        }
        // ---- B tile load ----
        float4 bv;
        if (SPLIT_B) {
            bv = (bn < 64) ? *(const float4*)(Wa + (size_t)(k0 + bk) * 64 + bn)
                           : *(const float4*)(Wb + (size_t)(k0 + bk) * 64 + (bn - 64));
        } else {
            bv = *(const float4*)(Wa + (size_t)(k0 + bk) * 128 + bn);
        }

        __syncthreads();
        As[ak + 0][am] = av.x;
        As[ak + 1][am] = av.y;
        As[ak + 2][am] = av.z;
        As[ak + 3][am] = av.w;
        *(float4*)&Bs[bk][bn] = bv;
        __syncthreads();

#pragma unroll
        for (int kk = 0; kk < 8; kk++) {
            ulonglong2 aA = *(const ulonglong2*)(&As[kk][ty * 8]);
            ulonglong2 aB = *(const ulonglong2*)(&As[kk][ty * 8 + 4]);
            float4 b0 = *(const float4*)(&Bs[kk][tx * 8]);
            float4 b1 = *(const float4*)(&Bs[kk][tx * 8 + 4]);
            ull a_[4] = { aA.x, aA.y, aB.x, aB.y };
            ull bb[8];
            bb[0] = pack2dup(b0.x); bb[1] = pack2dup(b0.y);
            bb[2] = pack2dup(b0.z); bb[3] = pack2dup(b0.w);
            bb[4] = pack2dup(b1.x); bb[5] = pack2dup(b1.y);
            bb[6] = pack2dup(b1.z); bb[7] = pack2dup(b1.w);
#pragma unroll
            for (int i2 = 0; i2 < 4; i2++)
#pragma unroll
                for (int j = 0; j < 8; j++)
                    acc2[i2][j] = ffma2(a_[i2], bb[j], acc2[i2][j]);
        }
    }

    // ---- epilogue ----
    const int cb = tx * 8;
    float ps[8], pq[8];
    if (STATS) {
#pragma unroll
        for (int j = 0; j < 8; j++) { ps[j] = 0.f; pq[j] = 0.f; }
    }

#pragma unroll
    for (int i2 = 0; i2 < 4; i2++) {
#pragma unroll
        for (int half = 0; half < 2; half++) {
            int r = m0 + ty * 8 + 2 * i2 + half;
            if (r < NN) {
                float v[8];
#pragma unroll
                for (int j = 0; j < 8; j++) {
                    float lo, hi;
                    unpack2(acc2[i2][j], lo, hi);
                    v[j] = half ? hi : lo;
                }
                if (BIAS) {
#pragma unroll
                    for (int j = 0; j < 8; j++) v[j] += __ldg(&bias[cb + j]);
                }
                if (STATS) {
#pragma unroll
                    for (int j = 0; j < 8; j++) { ps[j] += v[j]; pq[j] += v[j] * v[j]; }
                }
                if (!SPLIT_OUT) {
                    float4 q0 = make_float4(v[0], v[1], v[2], v[3]);
                    float4 q1 = make_float4(v[4], v[5], v[6], v[7]);
                    float* op = outA + (size_t)r * 128 + cb;
                    *(float4*)op = q0;
                    *(float4*)(op + 4) = q1;
                } else {
                    float s = (cb >= 64) ? __ldg(&dinv[r]) : 1.f;
                    float* op = (cb >= 64) ? (outB + (size_t)r * 64 + (cb - 64))
                                           : (outA + (size_t)r * 64 + cb);
                    float4 q0 = make_float4(v[0] * s, v[1] * s, v[2] * s, v[3] * s);
                    float4 q1 = make_float4(v[4] * s, v[5] * s, v[6] * s, v[7] * s);
                    *(float4*)op = q0;
                    *(float4*)(op + 4) = q1;
                }
            }
        }
    }

    if (STATS) {
        __syncthreads();
        if (tid < 128) { scol[tid] = 0.f; scq[tid] = 0.f; }
        __syncthreads();
#pragma unroll
        for (int j = 0; j < 8; j++) {
            atomicAdd(&scol[cb + j], ps[j]);
            atomicAdd(&scq[cb + j], pq[j]);
        }
        __syncthreads();
        if (tid < 128) {
            int sl = blockIdx.x & (NSLICE - 1);
            atomicAdd(&ssum[sl * 128 + tid], scol[tid]);
            atomicAdd(&ssq[sl * 128 + tid], scq[tid]);
        }
    }
}

// ------------------------- BN parameter reduce -------------------------------
template <int C>
__global__ void bnparam_k(const float* __restrict__ ssum, const float* __restrict__ ssq,
                          const float* __restrict__ gamma, const float* __restrict__ beta,
                          float* __restrict__ oa, float* __restrict__ oc)
{
    int c = threadIdx.x;
    if (c >= C) return;
    float s = 0.f, q = 0.f;
    for (int i = 0; i < NSLICE; i++) { s += ssum[i * C + c]; q += ssq[i * C + c]; }
    float m = s / (float)NN;
    float v = q / (float)NN - m * m;
    float a = gamma[c] * rsqrtf(v + BN_EPS);
    oa[c] = a;
    oc[c] = beta[c] - a * m;
}

// ------------------------- launcher ------------------------------------------
extern "C" void kernel_launch(void* const* d_in, const int* in_sizes, int n_in,
                              void* d_out, int out_size)
{
    const float* x  = (const float*)d_in[0];
    const int*   ei = (const int*)d_in[1];
    const float* W1 = (const float*)d_in[2];
    const float* b1 = (const float*)d_in[3];
    const float* W2 = (const float*)d_in[4];
    const float* b2 = (const float*)d_in[5];
    const float* W3 = (const float*)d_in[6];
    const float* b3 = (const float*)d_in[7];
    const float* ga1 = (const float*)d_in[8];
    const float* be1 = (const float*)d_in[9];
    const float* ga2 = (const float*)d_in[10];
    const float* be2 = (const float*)d_in[11];
    float* out = (float*)d_out;

    void *p_t1, *p_h1, *p_d2, *p_z2, *p_h2, *p_d3, *p_z3;
    void *p_dinv, *p_ptr, *p_src;
    void *p_sum1, *p_sq1, *p_sum2, *p_sq2, *p_a1, *p_c1, *p_a2, *p_c2;
    cudaGetSymbolAddress(&p_t1, g_t1);
    cudaGetSymbolAddress(&p_h1, g_h1);
    cudaGetSymbolAddress(&p_d2, g_d2);
    cudaGetSymbolAddress(&p_z2, g_z2);
    cudaGetSymbolAddress(&p_h2, g_h2);
    cudaGetSymbolAddress(&p_d3, g_d3);
    cudaGetSymbolAddress(&p_z3, g_z3);
    cudaGetSymbolAddress(&p_dinv, g_dinv);
    cudaGetSymbolAddress(&p_ptr, g_ptr);
    cudaGetSymbolAddress(&p_src, g_src);
    cudaGetSymbolAddress(&p_sum1, g_sum1);
    cudaGetSymbolAddress(&p_sq1, g_sq1);
    cudaGetSymbolAddress(&p_sum2, g_sum2);
    cudaGetSymbolAddress(&p_sq2, g_sq2);
    cudaGetSymbolAddress(&p_a1, g_a1);
    cudaGetSymbolAddress(&p_c1, g_c1);
    cudaGetSymbolAddress(&p_a2, g_a2);
    cudaGetSymbolAddress(&p_c2, g_c2);

    const int gN   = (NN + 255) / 256;
    const int gE   = (EE + 255) / 256;
    const int gSp  = (NN + 7) / 8;
    const int gGm  = (NN + 127) / 128;
    const int gScn = (NN + 1023) / 1024;   // 98

    // --- graph structure build (per launch, deterministic work) ---
    zero_k<<<gN, 256>>>();
    hist_k<<<gE, 256>>>(ei);
    dinv_k<<<gN, 256>>>();
    scanA_k<<<gScn, 1024>>>();
    scanB_k<<<1, 128>>>();
    scanC_k<<<gScn, 1024>>>();
    fill_k<<<gE, 256>>>(ei);

    // --- layer 1 ---
    // t1 = prop(x)  (64ch gather; dinv[src] applied in-loop)
    spmm_k<true, false, false><<<gSp, 256>>>(
        (const float2*)x, (const float*)p_dinv, (const int*)p_ptr, (const int*)p_src,
        nullptr, nullptr, (float2*)p_t1, nullptr, nullptr);
    // h1 = x@W1[0] + t1@W1[1] + b1   (+ BN stats)
    gemm_k<128, true, false, false, false, true, true><<<gGm, 256>>>(
        x, (const float*)p_t1, W1, nullptr, b1, nullptr, nullptr, nullptr,
        (float*)p_h1, nullptr, (float*)p_sum1, (float*)p_sq1);
    bnparam_k<128><<<1, 128>>>((const float*)p_sum1, (const float*)p_sq1, ga1, be1,
                               (float*)p_a1, (float*)p_c1);

    // --- layer 2 ---
    // [d2 | z2] = lrelu(bn(h1)) @ [W2[0] | W2[1]],  z2 pre-scaled by dinv[row]
    gemm_k<128, false, true, true, true, false, false><<<gGm, 256>>>(
        (const float*)p_h1, nullptr, W2, W2 + 128 * 64, nullptr,
        (const float*)p_a1, (const float*)p_c1, (const float*)p_dinv,
        (float*)p_d2, (float*)p_z2, nullptr, nullptr);
    // h2 = d2 + b2 - dinv[d]*sum z2[src]   (+ BN stats)
    spmm_k<false, true, true><<<gSp, 256>>>(
        (const float2*)p_z2, (const float*)p_dinv, (const int*)p_ptr, (const int*)p_src,
        (const float2*)p_d2, (const float2*)b2, (float2*)p_h2,
        (float*)p_sum2, (float*)p_sq2);
    bnparam_k<64><<<1, 64>>>((const float*)p_sum2, (const float*)p_sq2, ga2, be2,
                             (float*)p_a2, (float*)p_c2);

    // --- layer 3 ---
    gemm_k<64, false, true, true, true, false, false><<<gGm, 256>>>(
        (const float*)p_h2, nullptr, W3, W3 + 64 * 64, nullptr,
        (const float*)p_a2, (const float*)p_c2, (const float*)p_dinv,
        (float*)p_d3, (float*)p_z3, nullptr, nullptr);
    spmm_k<false, true, false><<<gSp, 256>>>(
        (const float2*)p_z3, (const float*)p_dinv, (const int*)p_ptr, (const int*)p_src,
        (const float2*)p_d3, (const float2*)b3, (float2*)out, nullptr, nullptr);

    (void)in_sizes; (void)n_in; (void)out_size;
}

// round 2
// speedup vs baseline: 1.0042x; 1.0042x over previous
#include <cuda_runtime.h>
#include <cuda_fp16.h>
#include <stdint.h>

#define NN 100000
#define EE 1600000
#define NSLICE 32
#define SLOPE 0.01f
#define BN_EPS 1e-5f

typedef unsigned long long ull;

// ------------------------- device scratch (no allocs allowed) ----------------
__device__ float g_t1[NN * 64];        // prop(x)
__device__ float g_h1[NN * 128];       // layer1 pre-BN
__device__ float g_d2[NN * 64];        // h1p @ W2[0]
__device__ float g_h2[NN * 64];        // layer2 pre-BN
__device__ float g_d3[NN * 64];
__device__ __align__(16) ull g_xh[NN * 16];   // fp16 dinv*x      (64 ch)
__device__ __align__(16) ull g_z2h[NN * 16];  // fp16 dinv*(h1p@W2[1])
__device__ __align__(16) ull g_z3h[NN * 16];  // fp16 dinv*(h2p@W3[1])
__device__ int   g_deg[NN];
__device__ int   g_cnt[NN];
__device__ int   g_ptr[NN + 1];
__device__ int   g_fill[NN];
__device__ int   g_src[EE];
__device__ float g_dinv[NN];
__device__ int   g_bsum[256];
__device__ float g_sum1[NSLICE * 128], g_sq1[NSLICE * 128];
__device__ float g_sum2[NSLICE * 64],  g_sq2[NSLICE * 64];
__device__ float g_a1[128], g_c1[128], g_a2[64], g_c2[64];

// ------------------------- small helpers -------------------------------------
__device__ __forceinline__ ull ffma2(ull a, ull b, ull c) {
    ull d;
    asm("fma.rn.f32x2 %0, %1, %2, %3;" : "=l"(d) : "l"(a), "l"(b), "l"(c));
    return d;
}
__device__ __forceinline__ ull pack2dup(float v) {
    ull r;
    asm("mov.b64 %0, {%1, %1};" : "=l"(r) : "f"(v));
    return r;
}
__device__ __forceinline__ void unpack2(ull v, float& lo, float& hi) {
    asm("mov.b64 {%0, %1}, %2;" : "=f"(lo), "=f"(hi) : "l"(v));
}

// ------------------------- setup kernels -------------------------------------
__global__ void zero_k() {
    int i = blockIdx.x * blockDim.x + threadIdx.x;
    if (i < NN) { g_deg[i] = 0; g_cnt[i] = 0; }
    if (i < NSLICE * 128) { g_sum1[i] = 0.f; g_sq1[i] = 0.f; }
    if (i < NSLICE * 64)  { g_sum2[i] = 0.f; g_sq2[i] = 0.f; }
}

__global__ void hist_k(const int* __restrict__ ei) {
    int e = blockIdx.x * blockDim.x + threadIdx.x;
    if (e < EE) {
        atomicAdd(&g_deg[ei[e]], 1);
        atomicAdd(&g_cnt[ei[EE + e]], 1);
    }
}

__global__ void dinv_k() {
    int i = blockIdx.x * blockDim.x + threadIdx.x;
    if (i < NN) {
        int d = g_deg[i];
        g_dinv[i] = (d > 0) ? rsqrtf((float)d) : 0.f;
    }
}

// xh[node][c] = fp16(dinv[node] * x[node][c])  -- 2 channels per thread
__global__ void cvtx_k(const float2* __restrict__ x2) {
    int i = blockIdx.x * blockDim.x + threadIdx.x;
    if (i < NN * 32) {
        int node = i >> 5;
        float di = g_dinv[node];
        float2 v = __ldg(&x2[i]);
        ((__half2*)g_xh)[i] = __floats2half2_rn(v.x * di, v.y * di);
    }
}

__device__ __forceinline__ int block_scan_incl(int v, int* sm) {
    int lane = threadIdx.x & 31, w = threadIdx.x >> 5;
    int incl = v;
#pragma unroll
    for (int o = 1; o < 32; o <<= 1) {
        int n = __shfl_up_sync(0xffffffffu, incl, o);
        if (lane >= o) incl += n;
    }
    if (lane == 31) sm[w] = incl;
    __syncthreads();
    if (w == 0) {
        int nw = blockDim.x >> 5;
        int s = (lane < nw) ? sm[lane] : 0;
#pragma unroll
        for (int o = 1; o < 32; o <<= 1) {
            int n = __shfl_up_sync(0xffffffffu, s, o);
            if (lane >= o) s += n;
        }
        sm[lane] = s;
    }
    __syncthreads();
    if (w > 0) incl += sm[w - 1];
    return incl;
}

__global__ void scanA_k() {
    __shared__ int sm[32];
    int i = blockIdx.x * 1024 + threadIdx.x;
    int v = (i < NN) ? g_cnt[i] : 0;
    int incl = block_scan_incl(v, sm);
    if (i < NN) g_ptr[i] = incl - v;             // local exclusive
    if (threadIdx.x == 1023) g_bsum[blockIdx.x] = incl;
}

__global__ void scanB_k() {
    __shared__ int sm[32];
    int t = threadIdx.x;
    int v = (t < 98) ? g_bsum[t] : 0;
    int incl = block_scan_incl(v, sm);
    if (t < 98) g_bsum[t] = incl - v;            // exclusive block offsets
}

__global__ void scanC_k() {
    int i = blockIdx.x * 1024 + threadIdx.x;
    if (i < NN) {
        int p = g_ptr[i] + g_bsum[blockIdx.x];
        g_ptr[i] = p;
        g_fill[i] = p;
    }
    if (i == 0) g_ptr[NN] = EE;
}

__global__ void fill_k(const int* __restrict__ ei) {
    int e = blockIdx.x * blockDim.x + threadIdx.x;
    if (e < EE) {
        int c = ei[EE + e];
        int pos = atomicAdd(&g_fill[c], 1);
        g_src[pos] = ei[e];
    }
}

// ------------------------- SpMM: one warp per destination node ---------------
// Features are fp16 (half2 per lane), pre-scaled by dinv[src].
// out[d] = (EPI2 ? direct[d] + bias : 0) - dinv[d] * sum_{s in in(d)} feat[s]
template <bool EPI2, bool STATS>
__global__ __launch_bounds__(256) void spmm_k(
    const __half2* __restrict__ feat, const float* __restrict__ dinv,
    const int* __restrict__ ptr, const int* __restrict__ srci,
    const float2* __restrict__ direct, const float2* __restrict__ bias2,
    float2* __restrict__ out, float* __restrict__ ssum, float* __restrict__ ssq)
{
    int lane = threadIdx.x & 31, warp = threadIdx.x >> 5;
    int d = blockIdx.x * 8 + warp;
    float2 res = make_float2(0.f, 0.f);
    bool valid = (d < NN);
    if (valid) {
        int e0 = __ldg(&ptr[d]);
        int e1 = __ldg(&ptr[d + 1]);
        float ax = 0.f, ay = 0.f;
        int e = e0;
        for (; e + 4 <= e1; e += 4) {
            int s0 = __ldg(&srci[e]);
            int s1 = __ldg(&srci[e + 1]);
            int s2 = __ldg(&srci[e + 2]);
            int s3 = __ldg(&srci[e + 3]);
            float2 f0 = __half22float2(__ldg(&feat[(size_t)s0 * 32 + lane]));
            float2 f1 = __half22float2(__ldg(&feat[(size_t)s1 * 32 + lane]));
            float2 f2 = __half22float2(__ldg(&feat[(size_t)s2 * 32 + lane]));
            float2 f3 = __half22float2(__ldg(&feat[(size_t)s3 * 32 + lane]));
            ax += f0.x + f1.x + f2.x + f3.x;
            ay += f0.y + f1.y + f2.y + f3.y;
        }
        for (; e < e1; e++) {
            int s = __ldg(&srci[e]);
            float2 f = __half22float2(__ldg(&feat[(size_t)s * 32 + lane]));
            ax += f.x;
            ay += f.y;
        }
        float di = __ldg(&dinv[d]);
        if (EPI2) {
            float2 dv = __ldg(&direct[(size_t)d * 32 + lane]);
            float2 b = __ldg(&bias2[lane]);
            res.x = dv.x + b.x - di * ax;
            res.y = dv.y + b.y - di * ay;
        } else {
            res.x = -di * ax;
            res.y = -di * ay;
        }
        out[(size_t)d * 32 + lane] = res;
    }
    if (STATS) {
        __shared__ float ss[64], sq[64];
        int t = threadIdx.x;
        if (t < 64) { ss[t] = 0.f; sq[t] = 0.f; }
        __syncthreads();
        if (valid) {
            atomicAdd(&ss[2 * lane], res.x);
            atomicAdd(&ss[2 * lane + 1], res.y);
            atomicAdd(&sq[2 * lane], res.x * res.x);
            atomicAdd(&sq[2 * lane + 1], res.y * res.y);
        }
        __syncthreads();
        if (t < 64) {
            int sl = blockIdx.x & (NSLICE - 1);
            atomicAdd(&ssum[sl * 64 + t], ss[t]);
            atomicAdd(&ssq[sl * 64 + t], sq[t]);
        }
    }
}

// ------------------------- SGEMM (128x128 tile, f32x2 inner loop) -----------
// C[m][n] = sum_k Atrans(A[m][k]) * B[k][n]   (Cout fixed = 128)
// TWO_A   : k<64 -> A1 (ld 64), k>=64 -> A2 (ld 64); else A1 with ld KTOT.
// BN_IN   : A element transform lrelu(bna[k]*v + bnc[k])
// SPLIT_B : B cols 0-63 from Wa (ld 64), 64-127 from Wb (ld 64); else Wa ld 128.
// SPLIT_OUT: cols 0-63 -> outA fp32 (ld 64); cols 64-127 -> outB fp16 half2-packed,
//            scaled by dinv[row]
// BIAS    : add bias[col] (only used with !SPLIT_OUT)
// STATS   : accumulate per-column sum / sum-sq of C into sliced globals
template <int KTOT, bool TWO_A, bool BN_IN, bool SPLIT_B, bool SPLIT_OUT, bool BIAS, bool STATS>
__global__ __launch_bounds__(256, 2) void gemm_k(
    const float* __restrict__ A1, const float* __restrict__ A2,
    const float* __restrict__ Wa, const float* __restrict__ Wb,
    const float* __restrict__ bias,
    const float* __restrict__ bna, const float* __restrict__ bnc,
    const float* __restrict__ dinv,
    float* __restrict__ outA, ull* __restrict__ outB,
    float* __restrict__ ssum, float* __restrict__ ssq)
{
    __shared__ float As[8][128];
    __shared__ float Bs[8][128];
    __shared__ float bnA[128], bnC[128];
    __shared__ float scol[128], scq[128];

    const int tid = threadIdx.x;
    const int tx = tid & 15, ty = tid >> 4;
    const int m0 = blockIdx.x * 128;

    if (BN_IN && tid < KTOT) { bnA[tid] = bna[tid]; bnC[tid] = bnc[tid]; }

    // loader indices
    const int am = tid >> 1;          // 0..127  (row within tile)
    const int ak = (tid & 1) * 4;     // 0 or 4  (k offset within BK)
    const int bk = tid >> 5;          // 0..7
    const int bn = (tid & 31) * 4;    // 0..124

    ull acc2[4][8];
#pragma unroll
    for (int i = 0; i < 4; i++)
#pragma unroll
        for (int j = 0; j < 8; j++) acc2[i][j] = 0ull;

    __syncthreads();   // bnA/bnC visible

    for (int k0 = 0; k0 < KTOT; k0 += 8) {
        // ---- A tile load (global -> regs) ----
        float4 av = make_float4(0.f, 0.f, 0.f, 0.f);
        int r = m0 + am;
        if (r < NN) {
            int kg = k0 + ak;
            const float* src;
            if (TWO_A)
                src = (kg < 64) ? (A1 + (size_t)r * 64 + kg)
                                : (A2 + (size_t)r * 64 + (kg - 64));
            else
                src = A1 + (size_t)r * KTOT + kg;
            av = *(const float4*)src;
        }
        if (BN_IN) {
            float* pv = &av.x;
#pragma unroll
            for (int i = 0; i < 4; i++) {
                float v = pv[i] * bnA[k0 + ak + i] + bnC[k0 + ak + i];
                pv[i] = (v >= 0.f) ? v : SLOPE * v;
            }
        }
        // ---- B tile load ----
        float4 bv;
        if (SPLIT_B) {
            bv = (bn < 64) ? *(const float4*)(Wa + (size_t)(k0 + bk) * 64 + bn)
                           : *(const float4*)(Wb + (size_t)(k0 + bk) * 64 + (bn - 64));
        } else {
            bv = *(const float4*)(Wa + (size_t)(k0 + bk) * 128 + bn);
        }

        __syncthreads();
        As[ak + 0][am] = av.x;
        As[ak + 1][am] = av.y;
        As[ak + 2][am] = av.z;
        As[ak + 3][am] = av.w;
        *(float4*)&Bs[bk][bn] = bv;
        __syncthreads();

#pragma unroll
        for (int kk = 0; kk < 8; kk++) {
            ulonglong2 aA = *(const ulonglong2*)(&As[kk][ty * 8]);
            ulonglong2 aB = *(const ulonglong2*)(&As[kk][ty * 8 + 4]);
            float4 b0 = *(const float4*)(&Bs[kk][tx * 8]);
            float4 b1 = *(const float4*)(&Bs[kk][tx * 8 + 4]);
            ull a_[4] = { aA.x, aA.y, aB.x, aB.y };
            ull bb[8];
            bb[0] = pack2dup(b0.x); bb[1] = pack2dup(b0.y);
            bb[2] = pack2dup(b0.z); bb[3] = pack2dup(b0.w);
            bb[4] = pack2dup(b1.x); bb[5] = pack2dup(b1.y);
            bb[6] = pack2dup(b1.z); bb[7] = pack2dup(b1.w);
#pragma unroll
            for (int i2 = 0; i2 < 4; i2++)
#pragma unroll
                for (int j = 0; j < 8; j++)
                    acc2[i2][j] = ffma2(a_[i2], bb[j], acc2[i2][j]);
        }
    }

    // ---- epilogue ----
    const int cb = tx * 8;
    float ps[8], pq[8];
    if (STATS) {
#pragma unroll
        for (int j = 0; j < 8; j++) { ps[j] = 0.f; pq[j] = 0.f; }
    }

#pragma unroll
    for (int i2 = 0; i2 < 4; i2++) {
#pragma unroll
        for (int half = 0; half < 2; half++) {
            int r = m0 + ty * 8 + 2 * i2 + half;
            if (r < NN) {
                float v[8];
#pragma unroll
                for (int j = 0; j < 8; j++) {
                    float lo, hi;
                    unpack2(acc2[i2][j], lo, hi);
                    v[j] = half ? hi : lo;
                }
                if (BIAS) {
#pragma unroll
                    for (int j = 0; j < 8; j++) v[j] += __ldg(&bias[cb + j]);
                }
                if (STATS) {
#pragma unroll
                    for (int j = 0; j < 8; j++) { ps[j] += v[j]; pq[j] += v[j] * v[j]; }
                }
                if (!SPLIT_OUT) {
                    float4 q0 = make_float4(v[0], v[1], v[2], v[3]);
                    float4 q1 = make_float4(v[4], v[5], v[6], v[7]);
                    float* op = outA + (size_t)r * 128 + cb;
                    *(float4*)op = q0;
                    *(float4*)(op + 4) = q1;
                } else if (cb < 64) {
                    float4 q0 = make_float4(v[0], v[1], v[2], v[3]);
                    float4 q1 = make_float4(v[4], v[5], v[6], v[7]);
                    float* op = outA + (size_t)r * 64 + cb;
                    *(float4*)op = q0;
                    *(float4*)(op + 4) = q1;
                } else {
                    // fp16 half2-packed z output, scaled by dinv[row]
                    float s = __ldg(&dinv[r]);
                    union { __half2 h[4]; ulonglong2 u; } pk;
#pragma unroll
                    for (int j = 0; j < 4; j++)
                        pk.h[j] = __floats2half2_rn(v[2 * j] * s, v[2 * j + 1] * s);
                    // half index within row: cb-64 .. cb-57 ; as ull units /4
                    *(ulonglong2*)(outB + (size_t)r * 16 + (cb - 64) / 4) = pk.u;
                }
            }
        }
    }

    if (STATS) {
        __syncthreads();
        if (tid < 128) { scol[tid] = 0.f; scq[tid] = 0.f; }
        __syncthreads();
#pragma unroll
        for (int j = 0; j < 8; j++) {
            atomicAdd(&scol[cb + j], ps[j]);
            atomicAdd(&scq[cb + j], pq[j]);
        }
        __syncthreads();
        if (tid < 128) {
            int sl = blockIdx.x & (NSLICE - 1);
            atomicAdd(&ssum[sl * 128 + tid], scol[tid]);
            atomicAdd(&ssq[sl * 128 + tid], scq[tid]);
        }
    }
}

// ------------------------- BN parameter reduce -------------------------------
template <int C>
__global__ void bnparam_k(const float* __restrict__ ssum, const float* __restrict__ ssq,
                          const float* __restrict__ gamma, const float* __restrict__ beta,
                          float* __restrict__ oa, float* __restrict__ oc)
{
    int c = threadIdx.x;
    if (c >= C) return;
    float s = 0.f, q = 0.f;
    for (int i = 0; i < NSLICE; i++) { s += ssum[i * C + c]; q += ssq[i * C + c]; }
    float m = s / (float)NN;
    float v = q / (float)NN - m * m;
    float a = gamma[c] * rsqrtf(v + BN_EPS);
    oa[c] = a;
    oc[c] = beta[c] - a * m;
}

// ------------------------- launcher ------------------------------------------
extern "C" void kernel_launch(void* const* d_in, const int* in_sizes, int n_in,
                              void* d_out, int out_size)
{
    const float* x  = (const float*)d_in[0];
    const int*   ei = (const int*)d_in[1];
    const float* W1 = (const float*)d_in[2];
    const float* b1 = (const float*)d_in[3];
    const float* W2 = (const float*)d_in[4];
    const float* b2 = (const float*)d_in[5];
    const float* W3 = (const float*)d_in[6];
    const float* b3 = (const float*)d_in[7];
    const float* ga1 = (const float*)d_in[8];
    const float* be1 = (const float*)d_in[9];
    const float* ga2 = (const float*)d_in[10];
    const float* be2 = (const float*)d_in[11];
    float* out = (float*)d_out;

    void *p_t1, *p_h1, *p_d2, *p_h2, *p_d3;
    void *p_xh, *p_z2h, *p_z3h;
    void *p_dinv, *p_ptr, *p_src;
    void *p_sum1, *p_sq1, *p_sum2, *p_sq2, *p_a1, *p_c1, *p_a2, *p_c2;
    cudaGetSymbolAddress(&p_t1, g_t1);
    cudaGetSymbolAddress(&p_h1, g_h1);
    cudaGetSymbolAddress(&p_d2, g_d2);
    cudaGetSymbolAddress(&p_h2, g_h2);
    cudaGetSymbolAddress(&p_d3, g_d3);
    cudaGetSymbolAddress(&p_xh, g_xh);
    cudaGetSymbolAddress(&p_z2h, g_z2h);
    cudaGetSymbolAddress(&p_z3h, g_z3h);
    cudaGetSymbolAddress(&p_dinv, g_dinv);
    cudaGetSymbolAddress(&p_ptr, g_ptr);
    cudaGetSymbolAddress(&p_src, g_src);
    cudaGetSymbolAddress(&p_sum1, g_sum1);
    cudaGetSymbolAddress(&p_sq1, g_sq1);
    cudaGetSymbolAddress(&p_sum2, g_sum2);
    cudaGetSymbolAddress(&p_sq2, g_sq2);
    cudaGetSymbolAddress(&p_a1, g_a1);
    cudaGetSymbolAddress(&p_c1, g_c1);
    cudaGetSymbolAddress(&p_a2, g_a2);
    cudaGetSymbolAddress(&p_c2, g_c2);

    const int gN   = (NN + 255) / 256;
    const int gE   = (EE + 255) / 256;
    const int gSp  = (NN + 7) / 8;
    const int gGm  = (NN + 127) / 128;
    const int gScn = (NN + 1023) / 1024;   // 98
    const int gCv  = (NN * 32 + 255) / 256;

    // --- graph structure build (per launch, deterministic work) ---
    zero_k<<<gN, 256>>>();
    hist_k<<<gE, 256>>>(ei);
    dinv_k<<<gN, 256>>>();
    cvtx_k<<<gCv, 256>>>((const float2*)x);
    scanA_k<<<gScn, 1024>>>();
    scanB_k<<<1, 128>>>();
    scanC_k<<<gScn, 1024>>>();
    fill_k<<<gE, 256>>>(ei);

    // --- layer 1 ---
    // t1 = prop(x)  (64ch fp16 gather; dinv[src] pre-folded into xh)
    spmm_k<false, false><<<gSp, 256>>>(
        (const __half2*)p_xh, (const float*)p_dinv, (const int*)p_ptr, (const int*)p_src,
        nullptr, nullptr, (float2*)p_t1, nullptr, nullptr);
    // h1 = x@W1[0] + t1@W1[1] + b1   (+ BN stats)
    gemm_k<128, true, false, false, false, true, true><<<gGm, 256>>>(
        x, (const float*)p_t1, W1, nullptr, b1, nullptr, nullptr, nullptr,
        (float*)p_h1, nullptr, (float*)p_sum1, (float*)p_sq1);
    bnparam_k<128><<<1, 128>>>((const float*)p_sum1, (const float*)p_sq1, ga1, be1,
                               (float*)p_a1, (float*)p_c1);

    // --- layer 2 ---
    // [d2 | z2h] = lrelu(bn(h1)) @ [W2[0] | W2[1]],  z2h fp16 pre-scaled by dinv[row]
    gemm_k<128, false, true, true, true, false, false><<<gGm, 256>>>(
        (const float*)p_h1, nullptr, W2, W2 + 128 * 64, nullptr,
        (const float*)p_a1, (const float*)p_c1, (const float*)p_dinv,
        (float*)p_d2, (ull*)p_z2h, nullptr, nullptr);
    // h2 = d2 + b2 - dinv[d]*sum z2[src]   (+ BN stats)
    spmm_k<true, true><<<gSp, 256>>>(
        (const __half2*)p_z2h, (const float*)p_dinv, (const int*)p_ptr, (const int*)p_src,
        (const float2*)p_d2, (const float2*)b2, (float2*)p_h2,
        (float*)p_sum2, (float*)p_sq2);
    bnparam_k<64><<<1, 64>>>((const float*)p_sum2, (const float*)p_sq2, ga2, be2,
                             (float*)p_a2, (float*)p_c2);

    // --- layer 3 ---
    gemm_k<64, false, true, true, true, false, false><<<gGm, 256>>>(
        (const float*)p_h2, nullptr, W3, W3 + 64 * 64, nullptr,
        (const float*)p_a2, (const float*)p_c2, (const float*)p_dinv,
        (float*)p_d3, (ull*)p_z3h, nullptr, nullptr);
    spmm_k<true, false><<<gSp, 256>>>(
        (const __half2*)p_z3h, (const float*)p_dinv, (const int*)p_ptr, (const int*)p_src,
        (const float2*)p_d3, (const float2*)b3, (float2*)out, nullptr, nullptr);

    (void)in_sizes; (void)n_in; (void)out_size;
}

// round 4
// speedup vs baseline: 1.1465x; 1.1417x over previous
#include <cuda_runtime.h>
#include <cuda_fp16.h>
#include <stdint.h>

#define NN 100000
#define EE 1600000
#define NSLICE 32
#define SLOPE 0.01f
#define BN_EPS 1e-5f
#define ASTR 24   // smem row stride in halves (48B): conflict-free LDSM

// ------------------------- device scratch ------------------------------------
__device__ __align__(16) __half g_xh[NN * 64];    // dinv*x fp16 (spmm1 feat)
__device__ __align__(16) __half g_xu[NN * 64];    // x fp16 (gemm1 A lo)
__device__ __align__(16) __half g_t1h[NN * 64];   // prop(x) fp16 (gemm1 A hi)
__device__ __align__(16) __half g_h1h[NN * 128];  // layer1 pre-BN fp16
__device__ __align__(16) __half g_h2h[NN * 64];   // layer2 pre-BN fp16
__device__ __align__(16) __half g_z2h[NN * 64];   // dinv*(h1p@W2[1]) fp16
__device__ __align__(16) __half g_z3h[NN * 64];
__device__ float g_d2[NN * 64];
__device__ float g_d3[NN * 64];
__device__ __align__(16) __half g_w1t[128 * 128]; // n-major fp16 weights
__device__ __align__(16) __half g_w2t[128 * 128];
__device__ __align__(16) __half g_w3t[128 * 64];
__device__ int   g_deg[NN];
__device__ int   g_cnt[NN];
__device__ int   g_ptr[NN + 1];
__device__ int   g_fill[NN];
__device__ int   g_src[EE];
__device__ float g_dinv[NN];
__device__ int   g_bsum[256];
__device__ float g_sum1[NSLICE * 128], g_sq1[NSLICE * 128];
__device__ float g_sum2[NSLICE * 64],  g_sq2[NSLICE * 64];
__device__ float g_a1[128], g_c1[128], g_a2[64], g_c2[64];

// ------------------------- setup kernels -------------------------------------
__global__ void zero_k() {
    int i = blockIdx.x * blockDim.x + threadIdx.x;
    if (i < NN) { g_deg[i] = 0; g_cnt[i] = 0; }
    if (i < NSLICE * 128) { g_sum1[i] = 0.f; g_sq1[i] = 0.f; }
    if (i < NSLICE * 64)  { g_sum2[i] = 0.f; g_sq2[i] = 0.f; }
}

__global__ void hist_k(const int* __restrict__ ei) {
    int e = blockIdx.x * blockDim.x + threadIdx.x;
    if (e < EE) {
        atomicAdd(&g_deg[ei[e]], 1);
        atomicAdd(&g_cnt[ei[EE + e]], 1);
    }
}

__global__ void dinv_k() {
    int i = blockIdx.x * blockDim.x + threadIdx.x;
    if (i < NN) {
        int d = g_deg[i];
        g_dinv[i] = (d > 0) ? rsqrtf((float)d) : 0.f;
    }
}

// xu = fp16(x), xh = fp16(dinv*x); 4 channels per thread
__global__ void cvtx_k(const float4* __restrict__ x4) {
    int i = blockIdx.x * blockDim.x + threadIdx.x;
    if (i < NN * 16) {
        int node = i >> 4;
        float di = g_dinv[node];
        float4 v = __ldg(&x4[i]);
        __half2* xu2 = (__half2*)g_xu;
        __half2* xh2 = (__half2*)g_xh;
        xu2[2 * i]     = __floats2half2_rn(v.x, v.y);
        xu2[2 * i + 1] = __floats2half2_rn(v.z, v.w);
        xh2[2 * i]     = __floats2half2_rn(v.x * di, v.y * di);
        xh2[2 * i + 1] = __floats2half2_rn(v.z * di, v.w * di);
    }
}

// Build n-major fp16 combined weight matrices
__global__ void cvtw_k(const float* __restrict__ W1, const float* __restrict__ W2,
                       const float* __restrict__ W3) {
    int i = blockIdx.x * blockDim.x + threadIdx.x;
    if (i < 16384) {                       // Wt1[n=cout][k=cin-combined]
        int n = i >> 7, k = i & 127;
        float v = (k < 64) ? W1[k * 128 + n] : W1[8192 + (k - 64) * 128 + n];
        g_w1t[n * 128 + k] = __float2half(v);
    } else if (i < 32768) {                // Wt2[n: 0-63=W2[0],64-127=W2[1]][k]
        int j = i - 16384; int n = j >> 7, k = j & 127;
        float v = (n < 64) ? W2[k * 64 + n] : W2[8192 + k * 64 + (n - 64)];
        g_w2t[n * 128 + k] = __float2half(v);
    } else if (i < 40960) {
        int j = i - 32768; int n = j >> 6, k = j & 63;
        float v = (n < 64) ? W3[k * 64 + n] : W3[4096 + k * 64 + (n - 64)];
        g_w3t[n * 64 + k] = __float2half(v);
    }
}

__device__ __forceinline__ int block_scan_incl(int v, int* sm) {
    int lane = threadIdx.x & 31, w = threadIdx.x >> 5;
    int incl = v;
#pragma unroll
    for (int o = 1; o < 32; o <<= 1) {
        int n = __shfl_up_sync(0xffffffffu, incl, o);
        if (lane >= o) incl += n;
    }
    if (lane == 31) sm[w] = incl;
    __syncthreads();
    if (w == 0) {
        int nw = blockDim.x >> 5;
        int s = (lane < nw) ? sm[lane] : 0;
#pragma unroll
        for (int o = 1; o < 32; o <<= 1) {
            int n = __shfl_up_sync(0xffffffffu, s, o);
            if (lane >= o) s += n;
        }
        sm[lane] = s;
    }
    __syncthreads();
    if (w > 0) incl += sm[w - 1];
    return incl;
}

__global__ void scanA_k() {
    __shared__ int sm[32];
    int i = blockIdx.x * 1024 + threadIdx.x;
    int v = (i < NN) ? g_cnt[i] : 0;
    int incl = block_scan_incl(v, sm);
    if (i < NN) g_ptr[i] = incl - v;
    if (threadIdx.x == 1023) g_bsum[blockIdx.x] = incl;
}

__global__ void scanB_k() {
    __shared__ int sm[32];
    int t = threadIdx.x;
    int v = (t < 98) ? g_bsum[t] : 0;
    int incl = block_scan_incl(v, sm);
    if (t < 98) g_bsum[t] = incl - v;
}

__global__ void scanC_k() {
    int i = blockIdx.x * 1024 + threadIdx.x;
    if (i < NN) {
        int p = g_ptr[i] + g_bsum[blockIdx.x];
        g_ptr[i] = p;
        g_fill[i] = p;
    }
    if (i == 0) g_ptr[NN] = EE;
}

__global__ void fill_k(const int* __restrict__ ei) {
    int e = blockIdx.x * blockDim.x + threadIdx.x;
    if (e < EE) {
        int c = ei[EE + e];
        int pos = atomicAdd(&g_fill[c], 1);
        g_src[pos] = ei[e];
    }
}

// ------------------------- SpMM: one warp per destination node ---------------
// feat fp16 half2/lane, pre-scaled by dinv[src].
// res = (EPI2 ? direct[d] + bias : 0) - dinv[d] * sum feat[src]
// OUTH: write fp16 half2, else fp32 float2.
template <bool EPI2, bool STATS, bool OUTH>
__global__ __launch_bounds__(256) void spmm_k(
    const __half2* __restrict__ feat, const float* __restrict__ dinv,
    const int* __restrict__ ptr, const int* __restrict__ srci,
    const float2* __restrict__ direct, const float2* __restrict__ bias2,
    void* __restrict__ outp, float* __restrict__ ssum, float* __restrict__ ssq)
{
    int lane = threadIdx.x & 31, warp = threadIdx.x >> 5;
    int d = blockIdx.x * 8 + warp;
    float2 res = make_float2(0.f, 0.f);
    bool valid = (d < NN);
    if (valid) {
        int e0 = __ldg(&ptr[d]);
        int e1 = __ldg(&ptr[d + 1]);
        float ax = 0.f, ay = 0.f;
        int e = e0;
        for (; e + 4 <= e1; e += 4) {
            int s0 = __ldg(&srci[e]);
            int s1 = __ldg(&srci[e + 1]);
            int s2 = __ldg(&srci[e + 2]);
            int s3 = __ldg(&srci[e + 3]);
            float2 f0 = __half22float2(__ldg(&feat[(size_t)s0 * 32 + lane]));
            float2 f1 = __half22float2(__ldg(&feat[(size_t)s1 * 32 + lane]));
            float2 f2 = __half22float2(__ldg(&feat[(size_t)s2 * 32 + lane]));
            float2 f3 = __half22float2(__ldg(&feat[(size_t)s3 * 32 + lane]));
            ax += f0.x + f1.x + f2.x + f3.x;
            ay += f0.y + f1.y + f2.y + f3.y;
        }
        for (; e < e1; e++) {
            int s = __ldg(&srci[e]);
            float2 f = __half22float2(__ldg(&feat[(size_t)s * 32 + lane]));
            ax += f.x;
            ay += f.y;
        }
        float di = __ldg(&dinv[d]);
        if (EPI2) {
            float2 dv = __ldg(&direct[(size_t)d * 32 + lane]);
            float2 b = __ldg(&bias2[lane]);
            res.x = dv.x + b.x - di * ax;
            res.y = dv.y + b.y - di * ay;
        } else {
            res.x = -di * ax;
            res.y = -di * ay;
        }
        if (OUTH)
            ((__half2*)outp)[(size_t)d * 32 + lane] = __floats2half2_rn(res.x, res.y);
        else
            ((float2*)outp)[(size_t)d * 32 + lane] = res;
    }
    if (STATS) {
        __shared__ float ss[64], sq[64];
        int t = threadIdx.x;
        if (t < 64) { ss[t] = 0.f; sq[t] = 0.f; }
        __syncthreads();
        if (valid) {
            atomicAdd(&ss[2 * lane], res.x);
            atomicAdd(&ss[2 * lane + 1], res.y);
            atomicAdd(&sq[2 * lane], res.x * res.x);
            atomicAdd(&sq[2 * lane + 1], res.y * res.y);
        }
        __syncthreads();
        if (t < 64) {
            int sl = blockIdx.x & (NSLICE - 1);
            atomicAdd(&ssum[sl * 64 + t], ss[t]);
            atomicAdd(&ssq[sl * 64 + t], sq[t]);
        }
    }
}

// ------------------------- HMMA GEMM (128x128 tile, m16n8k16) ---------------
// C[m][n] = sum_k f(A[m][k]) * Bt[n][k], fp16 inputs, fp32 accum.
// TWO_A : k<64 from A1 (ld 64), k>=64 from A2 (ld 64); else A1 ld KTOT.
// BN_IN : fragment transform lrelu(bna[k]*v + bnc[k]) in fp16.
// SPLIT_OUT: warp_n==0 (n<64) -> outD fp32 (ld 64);
//            warp_n==1 (n>=64) -> outZ fp16 * dinv[row] (ld 32 h2)
// else: outH fp16 (ld 64 h2) with BIAS.
// STATS : per-column sum/sumsq of (C+bias) over valid rows.
template <int KTOT, bool TWO_A, bool BN_IN, bool SPLIT_OUT, bool BIAS, bool STATS>
__global__ __launch_bounds__(256) void hgemm_k(
    const __half* __restrict__ A1, const __half* __restrict__ A2,
    const __half* __restrict__ Bt,
    const float* __restrict__ bias,
    const float* __restrict__ bna, const float* __restrict__ bnc,
    const float* __restrict__ dinv,
    __half2* __restrict__ outH, float* __restrict__ outD, __half2* __restrict__ outZ,
    float* __restrict__ ssum, float* __restrict__ ssq)
{
    constexpr int NSTEPS = KTOT / 16;
    __shared__ __align__(16) __half Asm[2][128 * ASTR];
    __shared__ __align__(16) __half Bsm[2][128 * ASTR];
    __shared__ __half2 bnA2[64], bnC2[64];
    __shared__ float scol[128], scq[128];

    const int tid = threadIdx.x;
    const int lane = tid & 31, wid = tid >> 5;
    const int warp_m = wid >> 1, warp_n = wid & 1;
    const int m0 = blockIdx.x * 128;

    if (BN_IN && tid < KTOT / 2) {
        bnA2[tid] = __floats2half2_rn(bna[2 * tid], bna[2 * tid + 1]);
        bnC2[tid] = __floats2half2_rn(bnc[2 * tid], bnc[2 * tid + 1]);
    }
    if (STATS && tid < 128) { scol[tid] = 0.f; scq[tid] = 0.f; }

    // global->smem loader indices (one 16B chunk per thread per operand)
    const int lrow = tid >> 1;            // 0..127
    const int lkc  = (tid & 1) * 8;       // 0 or 8 halves
    const int grow = m0 + lrow;
    const int growc = (grow < NN) ? grow : (NN - 1);
    const int asz = (grow < NN) ? 16 : 0;

    uint32_t sA = (uint32_t)__cvta_generic_to_shared(&Asm[0][0]);
    uint32_t sB = (uint32_t)__cvta_generic_to_shared(&Bsm[0][0]);
    const uint32_t dstA0 = sA + (lrow * ASTR + lkc) * 2;
    const uint32_t dstB0 = sB + (lrow * ASTR + lkc) * 2;
    const uint32_t BUFB = 128 * ASTR * 2;

    // ldmatrix lane offsets
    uint32_t aoff[2], boff[4];
#pragma unroll
    for (int mf = 0; mf < 2; mf++)
        aoff[mf] = sA + ((warp_m * 32 + mf * 16 + (lane & 15)) * ASTR + ((lane >> 4) << 3)) * 2;
#pragma unroll
    for (int nf4 = 0; nf4 < 4; nf4++)
        boff[nf4] = sB + ((warp_n * 64 + nf4 * 16 + ((lane >> 4) << 3) + (lane & 7)) * ASTR
                          + (((lane >> 3) & 1) << 3)) * 2;

    float c[2][8][4];
#pragma unroll
    for (int i = 0; i < 2; i++)
#pragma unroll
        for (int j = 0; j < 8; j++)
#pragma unroll
            for (int q = 0; q < 4; q++) c[i][j][q] = 0.f;

    auto load_stage = [&](int s) {
        int k = s * 16 + lkc;
        const __half* ap;
        if (TWO_A)
            ap = (k < 64) ? (A1 + (size_t)growc * 64 + k)
                          : (A2 + (size_t)growc * 64 + (k - 64));
        else
            ap = A1 + (size_t)growc * KTOT + k;
        uint32_t da = dstA0 + (uint32_t)(s & 1) * BUFB;
        asm volatile("cp.async.ca.shared.global [%0], [%1], 16, %2;\n"
                     :: "r"(da), "l"(ap), "r"(asz));
        const __half* bp = Bt + (size_t)lrow * KTOT + k;
        uint32_t db = dstB0 + (uint32_t)(s & 1) * BUFB;
        asm volatile("cp.async.ca.shared.global [%0], [%1], 16;\n"
                     :: "r"(db), "l"(bp));
    };

    load_stage(0);
    asm volatile("cp.async.commit_group;\n" ::: "memory");

    const __half2 slope2 = __float2half2_rn(SLOPE);

    for (int ks = 0; ks < NSTEPS; ks++) {
        if (ks + 1 < NSTEPS) {
            load_stage(ks + 1);
            asm volatile("cp.async.commit_group;\n" ::: "memory");
            asm volatile("cp.async.wait_group 1;\n" ::: "memory");
        } else {
            asm volatile("cp.async.wait_group 0;\n" ::: "memory");
        }
        __syncthreads();

        const uint32_t bufo = (uint32_t)(ks & 1) * BUFB;
        uint32_t a[2][4];
#pragma unroll
        for (int mf = 0; mf < 2; mf++) {
            asm volatile("ldmatrix.sync.aligned.m8n8.x4.shared.b16 {%0,%1,%2,%3}, [%4];\n"
                         : "=r"(a[mf][0]), "=r"(a[mf][1]), "=r"(a[mf][2]), "=r"(a[mf][3])
                         : "r"(aoff[mf] + bufo));
        }
        if (BN_IN) {
            int kp = (ks << 3) + (lane & 3);
            __half2 alo = bnA2[kp], clo = bnC2[kp];
            __half2 ahi = bnA2[kp + 4], chi = bnC2[kp + 4];
#pragma unroll
            for (int mf = 0; mf < 2; mf++) {
                __half2* av = (__half2*)a[mf];
                __half2 t;
                t = __hfma2(av[0], alo, clo); av[0] = __hmax2(t, __hmul2(t, slope2));
                t = __hfma2(av[1], alo, clo); av[1] = __hmax2(t, __hmul2(t, slope2));
                t = __hfma2(av[2], ahi, chi); av[2] = __hmax2(t, __hmul2(t, slope2));
                t = __hfma2(av[3], ahi, chi); av[3] = __hmax2(t, __hmul2(t, slope2));
            }
        }
        uint32_t b[8][2];
#pragma unroll
        for (int nf4 = 0; nf4 < 4; nf4++) {
            asm volatile("ldmatrix.sync.aligned.m8n8.x4.shared.b16 {%0,%1,%2,%3}, [%4];\n"
                         : "=r"(b[nf4 * 2][0]), "=r"(b[nf4 * 2][1]),
                           "=r"(b[nf4 * 2 + 1][0]), "=r"(b[nf4 * 2 + 1][1])
                         : "r"(boff[nf4] + bufo));
        }
#pragma unroll
        for (int mf = 0; mf < 2; mf++)
#pragma unroll
            for (int nf = 0; nf < 8; nf++) {
                asm volatile(
                    "mma.sync.aligned.m16n8k16.row.col.f32.f16.f16.f32 "
                    "{%0,%1,%2,%3}, {%4,%5,%6,%7}, {%8,%9}, {%0,%1,%2,%3};\n"
                    : "+f"(c[mf][nf][0]), "+f"(c[mf][nf][1]),
                      "+f"(c[mf][nf][2]), "+f"(c[mf][nf][3])
                    : "r"(a[mf][0]), "r"(a[mf][1]), "r"(a[mf][2]), "r"(a[mf][3]),
                      "r"(b[nf][0]), "r"(b[nf][1]));
            }
        __syncthreads();
    }

    // ---- epilogue ----
#pragma unroll
    for (int nf = 0; nf < 8; nf++) {
        const int col = warp_n * 64 + nf * 8 + (lane & 3) * 2;
        float se = 0.f, so = 0.f, qe = 0.f, qo = 0.f;
#pragma unroll
        for (int mf = 0; mf < 2; mf++) {
            int r0 = m0 + warp_m * 32 + mf * 16 + (lane >> 2);
            int r1 = r0 + 8;
            float v0 = c[mf][nf][0], v1 = c[mf][nf][1];
            float v2 = c[mf][nf][2], v3 = c[mf][nf][3];
            if (BIAS) {
                float be = __ldg(&bias[col]), bo = __ldg(&bias[col + 1]);
                v0 += be; v1 += bo; v2 += be; v3 += bo;
            }
            if (!SPLIT_OUT) {
                if (r0 < NN) outH[(size_t)r0 * 64 + (col >> 1)] = __floats2half2_rn(v0, v1);
                if (r1 < NN) outH[(size_t)r1 * 64 + (col >> 1)] = __floats2half2_rn(v2, v3);
            } else if (warp_n == 0) {
                // cols 0-63 -> fp32 direct term
                if (r0 < NN) *(float2*)(outD + (size_t)r0 * 64 + col) = make_float2(v0, v1);
                if (r1 < NN) *(float2*)(outD + (size_t)r1 * 64 + col) = make_float2(v2, v3);
            } else {
                // cols 64-127 -> fp16 z operand, pre-scaled by dinv[row]
                int cz = col - 64;
                if (r0 < NN) {
                    float s = __ldg(&dinv[r0]);
                    outZ[(size_t)r0 * 32 + (cz >> 1)] = __floats2half2_rn(v0 * s, v1 * s);
                }
                if (r1 < NN) {
                    float s = __ldg(&dinv[r1]);
                    outZ[(size_t)r1 * 32 + (cz >> 1)] = __floats2half2_rn(v2 * s, v3 * s);
                }
            }
            if (STATS) {
                if (r0 < NN) { se += v0; so += v1; qe += v0 * v0; qo += v1 * v1; }
                if (r1 < NN) { se += v2; so += v3; qe += v2 * v2; qo += v3 * v3; }
            }
        }
        if (STATS) {
#pragma unroll
            for (int o = 16; o >= 4; o >>= 1) {
                se += __shfl_xor_sync(0xffffffffu, se, o);
                so += __shfl_xor_sync(0xffffffffu, so, o);
                qe += __shfl_xor_sync(0xffffffffu, qe, o);
                qo += __shfl_xor_sync(0xffffffffu, qo, o);
            }
            if (lane < 4) {
                atomicAdd(&scol[col], se);
                atomicAdd(&scol[col + 1], so);
                atomicAdd(&scq[col], qe);
                atomicAdd(&scq[col + 1], qo);
            }
        }
    }
    if (STATS) {
        __syncthreads();
        if (tid < 128) {
            int sl = blockIdx.x & (NSLICE - 1);
            atomicAdd(&ssum[sl * 128 + tid], scol[tid]);
            atomicAdd(&ssq[sl * 128 + tid], scq[tid]);
        }
    }
}

// ------------------------- BN parameter reduce -------------------------------
template <int C>
__global__ void bnparam_k(const float* __restrict__ ssum, const float* __restrict__ ssq,
                          const float* __restrict__ gamma, const float* __restrict__ beta,
                          float* __restrict__ oa, float* __restrict__ oc)
{
    int c = threadIdx.x;
    if (c >= C) return;
    float s = 0.f, q = 0.f;
    for (int i = 0; i < NSLICE; i++) { s += ssum[i * C + c]; q += ssq[i * C + c]; }
    float m = s / (float)NN;
    float v = q / (float)NN - m * m;
    float a = gamma[c] * rsqrtf(v + BN_EPS);
    oa[c] = a;
    oc[c] = beta[c] - a * m;
}

// ------------------------- launcher ------------------------------------------
extern "C" void kernel_launch(void* const* d_in, const int* in_sizes, int n_in,
                              void* d_out, int out_size)
{
    const float* x  = (const float*)d_in[0];
    const int*   ei = (const int*)d_in[1];
    const float* W1 = (const float*)d_in[2];
    const float* b1 = (const float*)d_in[3];
    const float* W2 = (const float*)d_in[4];
    const float* b2 = (const float*)d_in[5];
    const float* W3 = (const float*)d_in[6];
    const float* b3 = (const float*)d_in[7];
    const float* ga1 = (const float*)d_in[8];
    const float* be1 = (const float*)d_in[9];
    const float* ga2 = (const float*)d_in[10];
    const float* be2 = (const float*)d_in[11];
    float* out = (float*)d_out;

    void *p_xh, *p_xu, *p_t1h, *p_h1h, *p_h2h, *p_z2h, *p_z3h, *p_d2, *p_d3;
    void *p_w1t, *p_w2t, *p_w3t;
    void *p_dinv, *p_ptr, *p_src;
    void *p_sum1, *p_sq1, *p_sum2, *p_sq2, *p_a1, *p_c1, *p_a2, *p_c2;
    cudaGetSymbolAddress(&p_xh, g_xh);
    cudaGetSymbolAddress(&p_xu, g_xu);
    cudaGetSymbolAddress(&p_t1h, g_t1h);
    cudaGetSymbolAddress(&p_h1h, g_h1h);
    cudaGetSymbolAddress(&p_h2h, g_h2h);
    cudaGetSymbolAddress(&p_z2h, g_z2h);
    cudaGetSymbolAddress(&p_z3h, g_z3h);
    cudaGetSymbolAddress(&p_d2, g_d2);
    cudaGetSymbolAddress(&p_d3, g_d3);
    cudaGetSymbolAddress(&p_w1t, g_w1t);
    cudaGetSymbolAddress(&p_w2t, g_w2t);
    cudaGetSymbolAddress(&p_w3t, g_w3t);
    cudaGetSymbolAddress(&p_dinv, g_dinv);
    cudaGetSymbolAddress(&p_ptr, g_ptr);
    cudaGetSymbolAddress(&p_src, g_src);
    cudaGetSymbolAddress(&p_sum1, g_sum1);
    cudaGetSymbolAddress(&p_sq1, g_sq1);
    cudaGetSymbolAddress(&p_sum2, g_sum2);
    cudaGetSymbolAddress(&p_sq2, g_sq2);
    cudaGetSymbolAddress(&p_a1, g_a1);
    cudaGetSymbolAddress(&p_c1, g_c1);
    cudaGetSymbolAddress(&p_a2, g_a2);
    cudaGetSymbolAddress(&p_c2, g_c2);

    const int gN   = (NN + 255) / 256;
    const int gE   = (EE + 255) / 256;
    const int gSp  = (NN + 7) / 8;
    const int gGm  = (NN + 127) / 128;     // 782
    const int gScn = (NN + 1023) / 1024;   // 98
    const int gCv  = (NN * 16 + 255) / 256;

    // --- setup ---
    zero_k<<<gN, 256>>>();
    hist_k<<<gE, 256>>>(ei);
    dinv_k<<<gN, 256>>>();
    cvtw_k<<<160, 256>>>(W1, W2, W3);
    cvtx_k<<<gCv, 256>>>((const float4*)x);
    scanA_k<<<gScn, 1024>>>();
    scanB_k<<<1, 128>>>();
    scanC_k<<<gScn, 1024>>>();
    fill_k<<<gE, 256>>>(ei);

    // --- layer 1 ---
    spmm_k<false, false, true><<<gSp, 256>>>(
        (const __half2*)p_xh, (const float*)p_dinv, (const int*)p_ptr, (const int*)p_src,
        nullptr, nullptr, p_t1h, nullptr, nullptr);
    hgemm_k<128, true, false, false, true, true><<<gGm, 256>>>(
        (const __half*)p_xu, (const __half*)p_t1h, (const __half*)p_w1t,
        b1, nullptr, nullptr, nullptr,
        (__half2*)p_h1h, nullptr, nullptr, (float*)p_sum1, (float*)p_sq1);
    bnparam_k<128><<<1, 128>>>((const float*)p_sum1, (const float*)p_sq1, ga1, be1,
                               (float*)p_a1, (float*)p_c1);

    // --- layer 2 ---
    hgemm_k<128, false, true, true, false, false><<<gGm, 256>>>(
        (const __half*)p_h1h, nullptr, (const __half*)p_w2t,
        nullptr, (const float*)p_a1, (const float*)p_c1, (const float*)p_dinv,
        nullptr, (float*)p_d2, (__half2*)p_z2h, nullptr, nullptr);
    spmm_k<true, true, true><<<gSp, 256>>>(
        (const __half2*)p_z2h, (const float*)p_dinv, (const int*)p_ptr, (const int*)p_src,
        (const float2*)p_d2, (const float2*)b2, p_h2h,
        (float*)p_sum2, (float*)p_sq2);
    bnparam_k<64><<<1, 64>>>((const float*)p_sum2, (const float*)p_sq2, ga2, be2,
                             (float*)p_a2, (float*)p_c2);

    // --- layer 3 ---
    hgemm_k<64, false, true, true, false, false><<<gGm, 256>>>(
        (const __half*)p_h2h, nullptr, (const __half*)p_w3t,
        nullptr, (const float*)p_a2, (const float*)p_c2, (const float*)p_dinv,
        nullptr, (float*)p_d3, (__half2*)p_z3h, nullptr, nullptr);
    spmm_k<true, false, false><<<gSp, 256>>>(
        (const __half2*)p_z3h, (const float*)p_dinv, (const int*)p_ptr, (const int*)p_src,
        (const float2*)p_d3, (const float2*)b3, out, nullptr, nullptr);

    (void)in_sizes; (void)n_in; (void)out_size;
}

// round 5
// speedup vs baseline: 1.6358x; 1.4267x over previous
#include <cuda_runtime.h>
#include <cuda_fp16.h>
#include <stdint.h>

#define NN 100000
#define EE 1600000
#define NSLICE 32
#define SLOPE 0.01f
#define BN_EPS 1e-5f
#define ASTR 24   // smem row stride in halves (48B): conflict-free LDSM
#define GZERO 391 // (NN+255)/256 blocks for the zero part of init_k

// ------------------------- device scratch ------------------------------------
__device__ __align__(16) __half g_xh[NN * 64];    // dinv*x fp16 (spmm1 feat)
__device__ __align__(16) __half g_xu[NN * 64];    // x fp16 (gemm1 A lo)
__device__ __align__(16) __half g_t1h[NN * 64];   // prop(x) fp16 (gemm1 A hi)
__device__ __align__(16) __half g_h1h[NN * 128];  // layer1 pre-BN fp16
__device__ __align__(16) __half g_h2h[NN * 64];   // layer2 pre-BN fp16
__device__ __align__(16) __half g_z2h[NN * 64];   // dinv*(h1p@W2[1]) fp16
__device__ __align__(16) __half g_z3h[NN * 64];
__device__ float g_d2[NN * 64];
__device__ float g_d3[NN * 64];
__device__ __align__(16) __half g_w1t[128 * 128]; // n-major fp16 weights
__device__ __align__(16) __half g_w2t[128 * 128];
__device__ __align__(16) __half g_w3t[128 * 64];
__device__ int   g_deg[NN];
__device__ int   g_cnt[NN];
__device__ int   g_ptr[NN + 1];
__device__ int   g_fill[NN];
__device__ int   g_src[EE];
__device__ float g_dinv[NN];
__device__ int   g_bsum[256];
__device__ float g_sum1[NSLICE * 128], g_sq1[NSLICE * 128];
__device__ float g_sum2[NSLICE * 64],  g_sq2[NSLICE * 64];

// ------------------------- setup kernels -------------------------------------
// init_k: blocks [0,GZERO) zero counters/stats; blocks [GZERO,GZERO+160) convert weights
__global__ void init_k(const float* __restrict__ W1, const float* __restrict__ W2,
                       const float* __restrict__ W3) {
    int b = blockIdx.x;
    if (b < GZERO) {
        int i = b * 256 + threadIdx.x;
        if (i < NN) { g_deg[i] = 0; g_cnt[i] = 0; }
        if (i < NSLICE * 128) { g_sum1[i] = 0.f; g_sq1[i] = 0.f; }
        if (i < NSLICE * 64)  { g_sum2[i] = 0.f; g_sq2[i] = 0.f; }
    } else {
        int i = (b - GZERO) * 256 + threadIdx.x;
        if (i < 16384) {                       // Wt1[n=cout][k=cin-combined]
            int n = i >> 7, k = i & 127;
            float v = (k < 64) ? W1[k * 128 + n] : W1[8192 + (k - 64) * 128 + n];
            g_w1t[n * 128 + k] = __float2half(v);
        } else if (i < 32768) {                // Wt2[n: 0-63=W2[0],64-127=W2[1]][k]
            int j = i - 16384; int n = j >> 7, k = j & 127;
            float v = (n < 64) ? W2[k * 64 + n] : W2[8192 + k * 64 + (n - 64)];
            g_w2t[n * 128 + k] = __float2half(v);
        } else if (i < 40960) {
            int j = i - 32768; int n = j >> 6, k = j & 63;
            float v = (n < 64) ? W3[k * 64 + n] : W3[4096 + k * 64 + (n - 64)];
            g_w3t[n * 64 + k] = __float2half(v);
        }
    }
}

__global__ void hist_k(const int* __restrict__ ei) {
    int e = blockIdx.x * blockDim.x + threadIdx.x;
    if (e < EE) {
        atomicAdd(&g_deg[ei[e]], 1);
        atomicAdd(&g_cnt[ei[EE + e]], 1);
    }
}

// dinv + xu/xh conversion fused; 4 channels per thread (16 threads per node)
__global__ void cvtx_k(const float4* __restrict__ x4) {
    int i = blockIdx.x * blockDim.x + threadIdx.x;
    if (i < NN * 16) {
        int node = i >> 4;
        int d = __ldg(&g_deg[node]);
        float di = (d > 0) ? rsqrtf((float)d) : 0.f;
        if ((i & 15) == 0) g_dinv[node] = di;
        float4 v = __ldg(&x4[i]);
        __half2* xu2 = (__half2*)g_xu;
        __half2* xh2 = (__half2*)g_xh;
        xu2[2 * i]     = __floats2half2_rn(v.x, v.y);
        xu2[2 * i + 1] = __floats2half2_rn(v.z, v.w);
        xh2[2 * i]     = __floats2half2_rn(v.x * di, v.y * di);
        xh2[2 * i + 1] = __floats2half2_rn(v.z * di, v.w * di);
    }
}

__device__ __forceinline__ int block_scan_incl(int v, int* sm) {
    int lane = threadIdx.x & 31, w = threadIdx.x >> 5;
    int incl = v;
#pragma unroll
    for (int o = 1; o < 32; o <<= 1) {
        int n = __shfl_up_sync(0xffffffffu, incl, o);
        if (lane >= o) incl += n;
    }
    if (lane == 31) sm[w] = incl;
    __syncthreads();
    if (w == 0) {
        int nw = blockDim.x >> 5;
        int s = (lane < nw) ? sm[lane] : 0;
#pragma unroll
        for (int o = 1; o < 32; o <<= 1) {
            int n = __shfl_up_sync(0xffffffffu, s, o);
            if (lane >= o) s += n;
        }
        sm[lane] = s;
    }
    __syncthreads();
    if (w > 0) incl += sm[w - 1];
    return incl;
}

__global__ void scanA_k() {
    __shared__ int sm[32];
    int i = blockIdx.x * 1024 + threadIdx.x;
    int v = (i < NN) ? g_cnt[i] : 0;
    int incl = block_scan_incl(v, sm);
    if (i < NN) g_ptr[i] = incl - v;
    if (threadIdx.x == 1023) g_bsum[blockIdx.x] = incl;
}

__global__ void scanB_k() {
    __shared__ int sm[32];
    int t = threadIdx.x;
    int v = (t < 98) ? g_bsum[t] : 0;
    int incl = block_scan_incl(v, sm);
    if (t < 98) g_bsum[t] = incl - v;
}

__global__ void scanC_k() {
    int i = blockIdx.x * 1024 + threadIdx.x;
    if (i < NN) {
        int p = g_ptr[i] + g_bsum[blockIdx.x];
        g_ptr[i] = p;
        g_fill[i] = p;
    }
    if (i == 0) g_ptr[NN] = EE;
}

__global__ void fill_k(const int* __restrict__ ei) {
    int e = blockIdx.x * blockDim.x + threadIdx.x;
    if (e < EE) {
        int c = ei[EE + e];
        int pos = atomicAdd(&g_fill[c], 1);
        g_src[pos] = ei[e];
    }
}

// ------------------------- SpMM: one warp per destination node ---------------
// feat fp16 half2/lane, pre-scaled by dinv[src].
// res = (EPI2 ? direct[d] + bias : 0) - dinv[d] * sum feat[src]
// OUTH: write fp16 half2, else fp32 float2.
template <bool EPI2, bool STATS, bool OUTH>
__global__ __launch_bounds__(256) void spmm_k(
    const __half2* __restrict__ feat, const float* __restrict__ dinv,
    const int* __restrict__ ptr, const int* __restrict__ srci,
    const float2* __restrict__ direct, const float2* __restrict__ bias2,
    void* __restrict__ outp, float* __restrict__ ssum, float* __restrict__ ssq)
{
    int lane = threadIdx.x & 31, warp = threadIdx.x >> 5;
    int d = blockIdx.x * 8 + warp;
    float2 res = make_float2(0.f, 0.f);
    bool valid = (d < NN);
    if (valid) {
        int e0 = __ldg(&ptr[d]);
        int e1 = __ldg(&ptr[d + 1]);
        float ax = 0.f, ay = 0.f;
        int e = e0;
        int eb = e0 + ((e1 - e0) & ~7);
        for (; e < eb; e += 8) {
            int s[8];
#pragma unroll
            for (int j = 0; j < 8; j++) s[j] = __ldg(&srci[e + j]);
            float2 f[8];
#pragma unroll
            for (int j = 0; j < 8; j++)
                f[j] = __half22float2(__ldg(&feat[(size_t)s[j] * 32 + lane]));
#pragma unroll
            for (int j = 0; j < 8; j++) { ax += f[j].x; ay += f[j].y; }
        }
        for (; e < e1; e++) {
            int s = __ldg(&srci[e]);
            float2 f = __half22float2(__ldg(&feat[(size_t)s * 32 + lane]));
            ax += f.x;
            ay += f.y;
        }
        float di = __ldg(&dinv[d]);
        if (EPI2) {
            float2 dv = __ldg(&direct[(size_t)d * 32 + lane]);
            float2 b = __ldg(&bias2[lane]);
            res.x = dv.x + b.x - di * ax;
            res.y = dv.y + b.y - di * ay;
        } else {
            res.x = -di * ax;
            res.y = -di * ay;
        }
        if (OUTH)
            ((__half2*)outp)[(size_t)d * 32 + lane] = __floats2half2_rn(res.x, res.y);
        else
            ((float2*)outp)[(size_t)d * 32 + lane] = res;
    }
    if (STATS) {
        __shared__ float ss[64], sq[64];
        int t = threadIdx.x;
        if (t < 64) { ss[t] = 0.f; sq[t] = 0.f; }
        __syncthreads();
        if (valid) {
            atomicAdd(&ss[2 * lane], res.x);
            atomicAdd(&ss[2 * lane + 1], res.y);
            atomicAdd(&sq[2 * lane], res.x * res.x);
            atomicAdd(&sq[2 * lane + 1], res.y * res.y);
        }
        __syncthreads();
        if (t < 64) {
            int sl = blockIdx.x & (NSLICE - 1);
            atomicAdd(&ssum[sl * 64 + t], ss[t]);
            atomicAdd(&ssq[sl * 64 + t], sq[t]);
        }
    }
}

// ------------------------- HMMA GEMM (128x128 tile, m16n8k16) ---------------
// C[m][n] = sum_k f(A[m][k]) * Bt[n][k], fp16 inputs, fp32 accum.
// TWO_A : k<64 from A1 (ld 64), k>=64 from A2 (ld 64); else A1 ld KTOT.
// BN_IN : BN params computed IN-BLOCK from raw stats (stat_sum/stat_sq, stride KTOT,
//         NSLICE slices) + gamma/beta; fragment transform lrelu(a*v+c) in fp16.
// SPLIT_OUT: warp_n==0 (n<64) -> outD fp32 (ld 64);
//            warp_n==1 (n>=64) -> outZ fp16 * dinv[row] (ld 32 h2)
// else: outH fp16 (ld 64 h2) with BIAS.
// STATS : per-column sum/sumsq of (C+bias) into osum/osq (sliced).
template <int KTOT, bool TWO_A, bool BN_IN, bool SPLIT_OUT, bool BIAS, bool STATS>
__global__ __launch_bounds__(256) void hgemm_k(
    const __half* __restrict__ A1, const __half* __restrict__ A2,
    const __half* __restrict__ Bt,
    const float* __restrict__ bias,
    const float* __restrict__ stat_sum, const float* __restrict__ stat_sq,
    const float* __restrict__ gamma, const float* __restrict__ beta,
    const float* __restrict__ dinv,
    __half2* __restrict__ outH, float* __restrict__ outD, __half2* __restrict__ outZ,
    float* __restrict__ osum, float* __restrict__ osq)
{
    constexpr int NSTEPS = KTOT / 16;
    __shared__ __align__(16) __half Asm[2][128 * ASTR];
    __shared__ __align__(16) __half Bsm[2][128 * ASTR];
    __shared__ __half2 bnA2[64], bnC2[64];
    __shared__ float scol[128], scq[128];

    const int tid = threadIdx.x;
    const int lane = tid & 31, wid = tid >> 5;
    const int warp_m = wid >> 1, warp_n = wid & 1;
    const int m0 = blockIdx.x * 128;

    if (BN_IN) {
        // fold the BN-parameter reduction into the block prologue
        if (tid < KTOT) {
            float s = 0.f, q = 0.f;
#pragma unroll 4
            for (int i = 0; i < NSLICE; i++) {
                s += __ldg(&stat_sum[i * KTOT + tid]);
                q += __ldg(&stat_sq[i * KTOT + tid]);
            }
            float m = s / (float)NN;
            float v = q / (float)NN - m * m;
            float a = __ldg(&gamma[tid]) * rsqrtf(v + BN_EPS);
            scol[tid] = a;
            scq[tid] = __ldg(&beta[tid]) - a * m;
        }
        __syncthreads();
        if (tid < KTOT / 2) {
            bnA2[tid] = __floats2half2_rn(scol[2 * tid], scol[2 * tid + 1]);
            bnC2[tid] = __floats2half2_rn(scq[2 * tid], scq[2 * tid + 1]);
        }
    }
    if (STATS && tid < 128) { scol[tid] = 0.f; scq[tid] = 0.f; }

    // global->smem loader indices (one 16B chunk per thread per operand)
    const int lrow = tid >> 1;            // 0..127
    const int lkc  = (tid & 1) * 8;       // 0 or 8 halves
    const int grow = m0 + lrow;
    const int growc = (grow < NN) ? grow : (NN - 1);
    const int asz = (grow < NN) ? 16 : 0;

    uint32_t sA = (uint32_t)__cvta_generic_to_shared(&Asm[0][0]);
    uint32_t sB = (uint32_t)__cvta_generic_to_shared(&Bsm[0][0]);
    const uint32_t dstA0 = sA + (lrow * ASTR + lkc) * 2;
    const uint32_t dstB0 = sB + (lrow * ASTR + lkc) * 2;
    const uint32_t BUFB = 128 * ASTR * 2;

    // ldmatrix lane offsets
    uint32_t aoff[2], boff[4];
#pragma unroll
    for (int mf = 0; mf < 2; mf++)
        aoff[mf] = sA + ((warp_m * 32 + mf * 16 + (lane & 15)) * ASTR + ((lane >> 4) << 3)) * 2;
#pragma unroll
    for (int nf4 = 0; nf4 < 4; nf4++)
        boff[nf4] = sB + ((warp_n * 64 + nf4 * 16 + ((lane >> 4) << 3) + (lane & 7)) * ASTR
                          + (((lane >> 3) & 1) << 3)) * 2;

    float c[2][8][4];
#pragma unroll
    for (int i = 0; i < 2; i++)
#pragma unroll
        for (int j = 0; j < 8; j++)
#pragma unroll
            for (int q = 0; q < 4; q++) c[i][j][q] = 0.f;

    auto load_stage = [&](int s) {
        int k = s * 16 + lkc;
        const __half* ap;
        if (TWO_A)
            ap = (k < 64) ? (A1 + (size_t)growc * 64 + k)
                          : (A2 + (size_t)growc * 64 + (k - 64));
        else
            ap = A1 + (size_t)growc * KTOT + k;
        uint32_t da = dstA0 + (uint32_t)(s & 1) * BUFB;
        asm volatile("cp.async.ca.shared.global [%0], [%1], 16, %2;\n"
                     :: "r"(da), "l"(ap), "r"(asz));
        const __half* bp = Bt + (size_t)lrow * KTOT + k;
        uint32_t db = dstB0 + (uint32_t)(s & 1) * BUFB;
        asm volatile("cp.async.ca.shared.global [%0], [%1], 16;\n"
                     :: "r"(db), "l"(bp));
    };

    load_stage(0);
    asm volatile("cp.async.commit_group;\n" ::: "memory");

    const __half2 slope2 = __float2half2_rn(SLOPE);
    __syncthreads();   // bnA2/bnC2 visible (no-op cost when !BN_IN)

    for (int ks = 0; ks < NSTEPS; ks++) {
        if (ks + 1 < NSTEPS) {
            load_stage(ks + 1);
            asm volatile("cp.async.commit_group;\n" ::: "memory");
            asm volatile("cp.async.wait_group 1;\n" ::: "memory");
        } else {
            asm volatile("cp.async.wait_group 0;\n" ::: "memory");
        }
        __syncthreads();

        const uint32_t bufo = (uint32_t)(ks & 1) * BUFB;
        uint32_t a[2][4];
#pragma unroll
        for (int mf = 0; mf < 2; mf++) {
            asm volatile("ldmatrix.sync.aligned.m8n8.x4.shared.b16 {%0,%1,%2,%3}, [%4];\n"
                         : "=r"(a[mf][0]), "=r"(a[mf][1]), "=r"(a[mf][2]), "=r"(a[mf][3])
                         : "r"(aoff[mf] + bufo));
        }
        if (BN_IN) {
            int kp = (ks << 3) + (lane & 3);
            __half2 alo = bnA2[kp], clo = bnC2[kp];
            __half2 ahi = bnA2[kp + 4], chi = bnC2[kp + 4];
#pragma unroll
            for (int mf = 0; mf < 2; mf++) {
                __half2* av = (__half2*)a[mf];
                __half2 t;
                t = __hfma2(av[0], alo, clo); av[0] = __hmax2(t, __hmul2(t, slope2));
                t = __hfma2(av[1], alo, clo); av[1] = __hmax2(t, __hmul2(t, slope2));
                t = __hfma2(av[2], ahi, chi); av[2] = __hmax2(t, __hmul2(t, slope2));
                t = __hfma2(av[3], ahi, chi); av[3] = __hmax2(t, __hmul2(t, slope2));
            }
        }
        uint32_t b[8][2];
#pragma unroll
        for (int nf4 = 0; nf4 < 4; nf4++) {
            asm volatile("ldmatrix.sync.aligned.m8n8.x4.shared.b16 {%0,%1,%2,%3}, [%4];\n"
                         : "=r"(b[nf4 * 2][0]), "=r"(b[nf4 * 2][1]),
                           "=r"(b[nf4 * 2 + 1][0]), "=r"(b[nf4 * 2 + 1][1])
                         : "r"(boff[nf4] + bufo));
        }
#pragma unroll
        for (int mf = 0; mf < 2; mf++)
#pragma unroll
            for (int nf = 0; nf < 8; nf++) {
                asm volatile(
                    "mma.sync.aligned.m16n8k16.row.col.f32.f16.f16.f32 "
                    "{%0,%1,%2,%3}, {%4,%5,%6,%7}, {%8,%9}, {%0,%1,%2,%3};\n"
                    : "+f"(c[mf][nf][0]), "+f"(c[mf][nf][1]),
                      "+f"(c[mf][nf][2]), "+f"(c[mf][nf][3])
                    : "r"(a[mf][0]), "r"(a[mf][1]), "r"(a[mf][2]), "r"(a[mf][3]),
                      "r"(b[nf][0]), "r"(b[nf][1]));
            }
        __syncthreads();
    }

    // ---- epilogue ----
#pragma unroll
    for (int nf = 0; nf < 8; nf++) {
        const int col = warp_n * 64 + nf * 8 + (lane & 3) * 2;
        float se = 0.f, so = 0.f, qe = 0.f, qo = 0.f;
#pragma unroll
        for (int mf = 0; mf < 2; mf++) {
            int r0 = m0 + warp_m * 32 + mf * 16 + (lane >> 2);
            int r1 = r0 + 8;
            float v0 = c[mf][nf][0], v1 = c[mf][nf][1];
            float v2 = c[mf][nf][2], v3 = c[mf][nf][3];
            if (BIAS) {
                float be = __ldg(&bias[col]), bo = __ldg(&bias[col + 1]);
                v0 += be; v1 += bo; v2 += be; v3 += bo;
            }
            if (!SPLIT_OUT) {
                if (r0 < NN) outH[(size_t)r0 * 64 + (col >> 1)] = __floats2half2_rn(v0, v1);
                if (r1 < NN) outH[(size_t)r1 * 64 + (col >> 1)] = __floats2half2_rn(v2, v3);
            } else if (warp_n == 0) {
                if (r0 < NN) *(float2*)(outD + (size_t)r0 * 64 + col) = make_float2(v0, v1);
                if (r1 < NN) *(float2*)(outD + (size_t)r1 * 64 + col) = make_float2(v2, v3);
            } else {
                int cz = col - 64;
                if (r0 < NN) {
                    float s = __ldg(&dinv[r0]);
                    outZ[(size_t)r0 * 32 + (cz >> 1)] = __floats2half2_rn(v0 * s, v1 * s);
                }
                if (r1 < NN) {
                    float s = __ldg(&dinv[r1]);
                    outZ[(size_t)r1 * 32 + (cz >> 1)] = __floats2half2_rn(v2 * s, v3 * s);
                }
            }
            if (STATS) {
                if (r0 < NN) { se += v0; so += v1; qe += v0 * v0; qo += v1 * v1; }
                if (r1 < NN) { se += v2; so += v3; qe += v2 * v2; qo += v3 * v3; }
            }
        }
        if (STATS) {
#pragma unroll
            for (int o = 16; o >= 4; o >>= 1) {
                se += __shfl_xor_sync(0xffffffffu, se, o);
                so += __shfl_xor_sync(0xffffffffu, so, o);
                qe += __shfl_xor_sync(0xffffffffu, qe, o);
                qo += __shfl_xor_sync(0xffffffffu, qo, o);
            }
            if (lane < 4) {
                atomicAdd(&scol[col], se);
                atomicAdd(&scol[col + 1], so);
                atomicAdd(&scq[col], qe);
                atomicAdd(&scq[col + 1], qo);
            }
        }
    }
    if (STATS) {
        __syncthreads();
        if (tid < 128) {
            int sl = blockIdx.x & (NSLICE - 1);
            atomicAdd(&osum[sl * 128 + tid], scol[tid]);
            atomicAdd(&osq[sl * 128 + tid], scq[tid]);
        }
    }
}

// ------------------------- launcher ------------------------------------------
extern "C" void kernel_launch(void* const* d_in, const int* in_sizes, int n_in,
                              void* d_out, int out_size)
{
    const float* x  = (const float*)d_in[0];
    const int*   ei = (const int*)d_in[1];
    const float* W1 = (const float*)d_in[2];
    const float* b1 = (const float*)d_in[3];
    const float* W2 = (const float*)d_in[4];
    const float* b2 = (const float*)d_in[5];
    const float* W3 = (const float*)d_in[6];
    const float* b3 = (const float*)d_in[7];
    const float* ga1 = (const float*)d_in[8];
    const float* be1 = (const float*)d_in[9];
    const float* ga2 = (const float*)d_in[10];
    const float* be2 = (const float*)d_in[11];
    float* out = (float*)d_out;

    void *p_xh, *p_xu, *p_t1h, *p_h1h, *p_h2h, *p_z2h, *p_z3h, *p_d2, *p_d3;
    void *p_w1t, *p_w2t, *p_w3t;
    void *p_dinv, *p_ptr, *p_src;
    void *p_sum1, *p_sq1, *p_sum2, *p_sq2;
    cudaGetSymbolAddress(&p_xh, g_xh);
    cudaGetSymbolAddress(&p_xu, g_xu);
    cudaGetSymbolAddress(&p_t1h, g_t1h);
    cudaGetSymbolAddress(&p_h1h, g_h1h);
    cudaGetSymbolAddress(&p_h2h, g_h2h);
    cudaGetSymbolAddress(&p_z2h, g_z2h);
    cudaGetSymbolAddress(&p_z3h, g_z3h);
    cudaGetSymbolAddress(&p_d2, g_d2);
    cudaGetSymbolAddress(&p_d3, g_d3);
    cudaGetSymbolAddress(&p_w1t, g_w1t);
    cudaGetSymbolAddress(&p_w2t, g_w2t);
    cudaGetSymbolAddress(&p_w3t, g_w3t);
    cudaGetSymbolAddress(&p_dinv, g_dinv);
    cudaGetSymbolAddress(&p_ptr, g_ptr);
    cudaGetSymbolAddress(&p_src, g_src);
    cudaGetSymbolAddress(&p_sum1, g_sum1);
    cudaGetSymbolAddress(&p_sq1, g_sq1);
    cudaGetSymbolAddress(&p_sum2, g_sum2);
    cudaGetSymbolAddress(&p_sq2, g_sq2);

    const int gE   = (EE + 255) / 256;
    const int gSp  = (NN + 7) / 8;
    const int gGm  = (NN + 127) / 128;     // 782
    const int gScn = (NN + 1023) / 1024;   // 98
    const int gCv  = (NN * 16 + 255) / 256;

    // --- setup (9 -> 7 launches) ---
    init_k<<<GZERO + 160, 256>>>(W1, W2, W3);
    hist_k<<<gE, 256>>>(ei);
    cvtx_k<<<gCv, 256>>>((const float4*)x);
    scanA_k<<<gScn, 1024>>>();
    scanB_k<<<1, 128>>>();
    scanC_k<<<gScn, 1024>>>();
    fill_k<<<gE, 256>>>(ei);

    // --- layer 1 ---
    spmm_k<false, false, true><<<gSp, 256>>>(
        (const __half2*)p_xh, (const float*)p_dinv, (const int*)p_ptr, (const int*)p_src,
        nullptr, nullptr, p_t1h, nullptr, nullptr);
    hgemm_k<128, true, false, false, true, true><<<gGm, 256>>>(
        (const __half*)p_xu, (const __half*)p_t1h, (const __half*)p_w1t,
        b1, nullptr, nullptr, nullptr, nullptr, nullptr,
        (__half2*)p_h1h, nullptr, nullptr, (float*)p_sum1, (float*)p_sq1);

    // --- layer 2 (BN1 folded into hgemm prologue) ---
    hgemm_k<128, false, true, true, false, false><<<gGm, 256>>>(
        (const __half*)p_h1h, nullptr, (const __half*)p_w2t,
        nullptr, (const float*)p_sum1, (const float*)p_sq1, ga1, be1,
        (const float*)p_dinv,
        nullptr, (float*)p_d2, (__half2*)p_z2h, nullptr, nullptr);
    spmm_k<true, true, true><<<gSp, 256>>>(
        (const __half2*)p_z2h, (const float*)p_dinv, (const int*)p_ptr, (const int*)p_src,
        (const float2*)p_d2, (const float2*)b2, p_h2h,
        (float*)p_sum2, (float*)p_sq2);

    // --- layer 3 (BN2 folded into hgemm prologue) ---
    hgemm_k<64, false, true, true, false, false><<<gGm, 256>>>(
        (const __half*)p_h2h, nullptr, (const __half*)p_w3t,
        nullptr, (const float*)p_sum2, (const float*)p_sq2, ga2, be2,
        (const float*)p_dinv,
        nullptr, (float*)p_d3, (__half2*)p_z3h, nullptr, nullptr);
    spmm_k<true, false, false><<<gSp, 256>>>(
        (const __half2*)p_z3h, (const float*)p_dinv, (const int*)p_ptr, (const int*)p_src,
        (const float2*)p_d3, (const float2*)b3, out, nullptr, nullptr);

    (void)in_sizes; (void)n_in; (void)out_size;
}